// round 4
// baseline (speedup 1.0000x reference)
#include <cuda_runtime.h>

// LearnedClassVectors: HU bucketize (10 bins) -> 12-dim embedding gather ->
// 4x4x4 patch unfold -> channel-major output (2, 768, 32, 32, 32) fp32.
//
// Shapes are fixed by the problem:
//   x:       (2,1,128,128,128) fp32   d_in[0]
//   vectors: (10,12)           fp32   d_in[1]
//   out:     (2,768,32,32,32)  fp32   50,331,648 elements
//
// Design: one thread per 16 consecutive w-voxels (a full gw-quad x pw group).
//   reads : 4x LDG.128, fully coalesced
//   writes: 48x STG.128 (float4 across 4 consecutive gw, one channel each),
//           warp-level: 4x fully packed 128B segments per store instruction.

static __device__ __forceinline__ int hu_bin(float v) {
    // searchsorted(edges, v, side='right') == count of edges <= v
    int b = 0;
    b += (v >= -1000.0f);
    b += (v >=   -75.0f);
    b += (v >=     0.0f);
    b += (v >=    15.0f);
    b += (v >=    25.0f);
    b += (v >=    40.0f);
    b += (v >=    50.0f);
    b += (v >=   200.0f);
    b += (v >=  1000.0f);
    return b;
}

__global__ __launch_bounds__(256)
void lcv_kernel(const float* __restrict__ x,
                const float* __restrict__ vectors,
                float* __restrict__ out) {
    // 10 rows x 12 floats; stride 12 spreads row bases across 8 smem banks
    __shared__ float s_vec[10 * 12];
    if (threadIdx.x < 120) s_vec[threadIdx.x] = vectors[threadIdx.x];
    __syncthreads();

    unsigned tid = blockIdx.x * blockDim.x + threadIdx.x;   // 0 .. 262143
    int tw = tid & 7;            // w-tile: covers w = 16*tw .. 16*tw+15
    unsigned r = tid >> 3;
    int h = r & 127; r >>= 7;
    int d = r & 127; r >>= 7;
    int b = (int)r;              // 0..1

    // ---- load 16 consecutive x values (64B, coalesced across warp) ----
    const float4* xp = (const float4*)(x +
        ((size_t)((b * 128 + d) * 128 + h) * 128 + (unsigned)tw * 16u));
    float4 xv[4];
    xv[0] = xp[0]; xv[1] = xp[1]; xv[2] = xp[2]; xv[3] = xp[3];

    // bins[gwi][pw]: voxel (gw = 4*tw + gwi, pw) is xv[gwi] component pw
    int bins[4][4];
#pragma unroll
    for (int g = 0; g < 4; g++) {
        bins[g][0] = hu_bin(xv[g].x);
        bins[g][1] = hu_bin(xv[g].y);
        bins[g][2] = hu_bin(xv[g].z);
        bins[g][3] = hu_bin(xv[g].w);
    }

    // ---- output addressing ----
    int gd = d >> 2, pd = d & 3;
    int gh = h >> 2, ph = h & 3;
    unsigned sp = (unsigned)gd * 1024u + (unsigned)gh * 32u + (unsigned)tw * 4u;
    float* ob = out + (size_t)b * (768u * 32768u) + sp;
    int chbase = (pd * 16 + ph * 4) * 12;   // + pw*12 + v

#pragma unroll
    for (int pw = 0; pw < 4; pw++) {
        const float* r0 = &s_vec[bins[0][pw] * 12];
        const float* r1 = &s_vec[bins[1][pw] * 12];
        const float* r2 = &s_vec[bins[2][pw] * 12];
        const float* r3 = &s_vec[bins[3][pw] * 12];

        // stage the 4 embedding rows into registers (fully unrolled -> regs)
        float a0[12], a1[12], a2[12], a3[12];
#pragma unroll
        for (int v = 0; v < 12; v++) {
            a0[v] = r0[v]; a1[v] = r1[v]; a2[v] = r2[v]; a3[v] = r3[v];
        }

        float* op = ob + (size_t)(chbase + pw * 12) * 32768u;
#pragma unroll
        for (int v = 0; v < 12; v++) {
            // 4 consecutive gw of one output channel -> one STG.128
            float4 o4 = make_float4(a0[v], a1[v], a2[v], a3[v]);
            *(float4*)op = o4;
            op += 32768;                     // next channel, same spatial
        }
    }
}

extern "C" void kernel_launch(void* const* d_in, const int* in_sizes, int n_in,
                              void* d_out, int out_size) {
    const float* x       = (const float*)d_in[0];
    const float* vectors = (const float*)d_in[1];
    float* out           = (float*)d_out;

    // 2*128*128*8 = 262144 threads
    lcv_kernel<<<1024, 256>>>(x, vectors, out);
}